// round 15
// baseline (speedup 1.0000x reference)
#include <cuda_runtime.h>
#include <cuda_fp16.h>

#define BATCH 2
#define SEQ   2048
#define DMODEL 2048
#define NH    32
#define NG    8
#define DKH   64
#define GDK   (NG * DKH)     // 512
#define NQKV  (DMODEL + 2 * GDK)   // 3072
#define MROWS (BATCH * SEQ)  // 4096
#define SCALE_Q 0.1803368801111204f   // 0.125 * log2(e)

// ---------------- scratch ----------------
__device__ __half g_xh   [MROWS * DMODEL];
__device__ __half g_QKVh [MROWS * NQKV];
__device__ __half g_Ch   [MROWS * DMODEL];
__device__ __half g_Wqkvt[NQKV * DMODEL];
__device__ __half g_Wot  [DMODEL * DMODEL];
__device__ float  g_bqkv [NQKV];

// ---------------- helpers ----------------
__device__ __forceinline__ unsigned smem_u32(const void* p) {
    unsigned a;
    asm("{ .reg .u64 t; cvta.to.shared.u64 t, %1; cvt.u32.u64 %0, t; }" : "=r"(a) : "l"(p));
    return a;
}
__device__ __forceinline__ void cp16(unsigned saddr, const void* g) {
    asm volatile("cp.async.cg.shared.global [%0], [%1], 16;" :: "r"(saddr), "l"(g));
}
#define CP_COMMIT() asm volatile("cp.async.commit_group;" ::: "memory")
#define CP_WAIT(n)  asm volatile("cp.async.wait_group %0;" :: "n"(n) : "memory")

__device__ __forceinline__ void ldm_x4(unsigned* r, unsigned saddr) {
    asm volatile("ldmatrix.sync.aligned.m8n8.x4.shared.b16 {%0,%1,%2,%3}, [%4];"
        : "=r"(r[0]), "=r"(r[1]), "=r"(r[2]), "=r"(r[3]) : "r"(saddr));
}
__device__ __forceinline__ void ldm_x4_t(unsigned* r, unsigned saddr) {
    asm volatile("ldmatrix.sync.aligned.m8n8.x4.trans.shared.b16 {%0,%1,%2,%3}, [%4];"
        : "=r"(r[0]), "=r"(r[1]), "=r"(r[2]), "=r"(r[3]) : "r"(saddr));
}
__device__ __forceinline__ void mma_f16(float* d, const unsigned* a, unsigned b0, unsigned b1) {
    asm volatile(
        "mma.sync.aligned.m16n8k16.row.col.f32.f16.f16.f32 "
        "{%0,%1,%2,%3}, {%4,%5,%6,%7}, {%8,%9}, {%0,%1,%2,%3};"
        : "+f"(d[0]), "+f"(d[1]), "+f"(d[2]), "+f"(d[3])
        : "r"(a[0]), "r"(a[1]), "r"(a[2]), "r"(a[3]), "r"(b0), "r"(b1));
}
__device__ __forceinline__ unsigned h2u(float a, float b) {
    __half2 h = __floats2half2_rn(a, b);
    return *reinterpret_cast<unsigned*>(&h);
}

// ---------------- prep kernels ----------------
__global__ __launch_bounds__(256) void cvt_half_kernel(
    const float* __restrict__ in, __half* __restrict__ out, int n4)
{
    int i = blockIdx.x * blockDim.x + threadIdx.x;
    if (i >= n4) return;
    float4 v = ((const float4*)in)[i];
    ((__half2*)out)[2 * i]     = __floats2half2_rn(v.x, v.y);
    ((__half2*)out)[2 * i + 1] = __floats2half2_rn(v.z, v.w);
}

__global__ __launch_bounds__(256) void transpose_all_kernel(
    const float* __restrict__ Wq, const float* __restrict__ Wk,
    const float* __restrict__ Wv, const float* __restrict__ Wo,
    __half* __restrict__ Wqkvt, __half* __restrict__ Wot)
{
    const float* W; __half* T; int N; float scale;
    switch (blockIdx.z) {
        case 0: W = Wq; T = Wqkvt;                                   N = DMODEL; scale = SCALE_Q; break;
        case 1: W = Wk; T = Wqkvt + (size_t)DMODEL * DMODEL;         N = GDK;    scale = 1.0f;    break;
        case 2: W = Wv; T = Wqkvt + (size_t)(DMODEL + GDK) * DMODEL; N = GDK;    scale = 1.0f;    break;
        default: W = Wo; T = Wot;                                    N = DMODEL; scale = 1.0f;    break;
    }
    int n0 = blockIdx.x * 32;
    if (n0 >= N) return;
    int k0 = blockIdx.y * 32;
    __shared__ float t[32][33];
    int tx = threadIdx.x & 31, ty = threadIdx.x >> 5;
#pragma unroll
    for (int s = 0; s < 4; s++)
        t[ty + 8 * s][tx] = W[(size_t)(k0 + ty + 8 * s) * N + n0 + tx];
    __syncthreads();
#pragma unroll
    for (int s = 0; s < 4; s++)
        T[(size_t)(n0 + ty + 8 * s) * DMODEL + k0 + tx] = __float2half(t[tx][ty + 8 * s] * scale);
}

__global__ __launch_bounds__(256) void fuse_bias_kernel(
    const float* __restrict__ bq, const float* __restrict__ bk,
    const float* __restrict__ bv, float* __restrict__ bqkv)
{
    int i = blockIdx.x * blockDim.x + threadIdx.x;
    if (i < DMODEL)                bqkv[i] = bq[i] * SCALE_Q;
    else if (i < DMODEL + GDK)     bqkv[i] = bk[i - DMODEL];
    else if (i < NQKV)             bqkv[i] = bv[i - DMODEL - GDK];
}

// ---------------- fp16 GEMM: 128x128 CTA, BK=64, 3-stage, 1 barrier/chunk ----------------
#define HST 72
#define TILE_H (128 * HST)
#define STG_H (2 * TILE_H)
#define GEMM_SMEM (3 * STG_H * 2)    // 110592 B

template <bool OUT_HALF>
__global__ __launch_bounds__(256, 2) void gemm_f16_kernel(
    const __half* __restrict__ A, const __half* __restrict__ Bt,
    const float* __restrict__ bias, void* __restrict__ Cout, int N, int K)
{
    extern __shared__ __half smh[];
    const unsigned sbase = smem_u32(smh);
    const int tid  = threadIdx.x;
    const int warp = tid >> 5;
    const int lane = tid & 31;
    const int grp  = lane >> 2;
    const int tig  = lane & 3;
    const int bm = blockIdx.y * 128;
    const int bn = blockIdx.x * 128;
    const int wm = (warp >> 2) * 64;
    const int wn = (warp & 3) * 32;

    const int lrow = (lane & 7) + 8 * ((lane >> 3) & 1);
    const int lseg = lane >> 4;
    const int brow = (lane & 7) + 8 * (lane >> 4);
    const int bseg = (lane >> 3) & 1;

    float acc[4][4][4];
#pragma unroll
    for (int mt = 0; mt < 4; mt++)
#pragma unroll
        for (int nt = 0; nt < 4; nt++)
#pragma unroll
            for (int f = 0; f < 4; f++) acc[mt][nt][f] = 0.0f;

    const int NC = K >> 6;

    auto load_chunk = [&](int kc) {
        unsigned ab = sbase + (kc % 3) * (STG_H * 2);
        unsigned bb = ab + TILE_H * 2;
        const __half* gA = A  + (size_t)bm * K + kc * 64;
        const __half* gB = Bt + (size_t)bn * K + kc * 64;
#pragma unroll
        for (int it = 0; it < 4; it++) {
            int i = tid + it * 256;
            int r = i >> 3, ch = i & 7;
            cp16(ab + (r * HST + ch * 8) * 2, gA + (size_t)r * K + ch * 8);
        }
#pragma unroll
        for (int it = 0; it < 4; it++) {
            int i = tid + it * 256;
            int r = i >> 3, ch = i & 7;
            cp16(bb + (r * HST + ch * 8) * 2, gB + (size_t)r * K + ch * 8);
        }
        CP_COMMIT();
    };

    load_chunk(0);
    if (NC > 1) load_chunk(1);
    for (int c = 0; c < NC; c++) {
        if (c < NC - 1) { CP_WAIT(1); }    // chunk c complete; c+1 may be in flight
        else            { CP_WAIT(0); }
        __syncthreads();                   // tile c visible; stage (c+2)%3 free
        if (c + 2 < NC) load_chunk(c + 2);

        const unsigned sA = sbase + (c % 3) * (STG_H * 2);
        const unsigned sB = sA + TILE_H * 2;
#pragma unroll
        for (int kb = 0; kb < 64; kb += 16) {
            unsigned a[4][4], bq[2][4];
#pragma unroll
            for (int mt = 0; mt < 4; mt++)
                ldm_x4(a[mt], sA + ((wm + mt * 16 + lrow) * HST + kb + 8 * lseg) * 2);
#pragma unroll
            for (int np = 0; np < 2; np++)
                ldm_x4(bq[np], sB + ((wn + np * 16 + brow) * HST + kb + 8 * bseg) * 2);
#pragma unroll
            for (int mt = 0; mt < 4; mt++)
#pragma unroll
                for (int np = 0; np < 2; np++) {
                    mma_f16(acc[mt][2 * np],     a[mt], bq[np][0], bq[np][1]);
                    mma_f16(acc[mt][2 * np + 1], a[mt], bq[np][2], bq[np][3]);
                }
        }
        // no trailing barrier: next iteration's sync provides it
    }

#pragma unroll
    for (int mt = 0; mt < 4; mt++) {
        int r0 = bm + wm + mt * 16 + grp;
#pragma unroll
        for (int nt = 0; nt < 4; nt++) {
            int c0 = bn + wn + nt * 8 + 2 * tig;
            float b0 = bias[c0], b1 = bias[c0 + 1];
            float v00 = acc[mt][nt][0] + b0, v01 = acc[mt][nt][1] + b1;
            float v10 = acc[mt][nt][2] + b0, v11 = acc[mt][nt][3] + b1;
            if (OUT_HALF) {
                __half* C = (__half*)Cout;
                *(unsigned*)(C + (size_t)r0 * N + c0)       = h2u(v00, v01);
                *(unsigned*)(C + (size_t)(r0 + 8) * N + c0) = h2u(v10, v11);
            } else {
                float* C = (float*)Cout;
                *(float2*)(C + (size_t)r0 * N + c0)       = make_float2(v00, v01);
                *(float2*)(C + (size_t)(r0 + 8) * N + c0) = make_float2(v10, v11);
            }
        }
    }
}

// ---------------- flash attention: 2 heads/block, 3-stage K/V, 1 barrier/tile ----------------
// smem: Q x2 + K x3 + V x3 = 8 tiles * 9216 B = 73728 B
#define AQST 72
#define ATILE_B (64 * AQST * 2)
#define ATTN_SMEM (8 * ATILE_B)

__global__ __launch_bounds__(256) void gqa_attn_f16_kernel(
    const __half* __restrict__ QKV, __half* __restrict__ O)
{
    extern __shared__ __half sh[];
    const unsigned sb = smem_u32(sh);
    const unsigned Qb0 = sb;                    // 2 head tiles
    const unsigned Kb0 = sb + 2 * ATILE_B;      // 3 stages
    const unsigned Vb0 = sb + 5 * ATILE_B;      // 3 stages

    const int h0 = blockIdx.y * 2;
    const int b  = blockIdx.z;
    const int g  = h0 >> 2;
    const int q0 = blockIdx.x * 64;
    const int tid  = threadIdx.x;
    const int warp = tid >> 5;
    const int hh   = warp >> 2;
    const int lane = tid & 31;
    const int grp  = lane >> 2;
    const int tig  = lane & 3;
    const int wq0 = (warp & 3) * 16;

    const int lrow = (lane & 7) + 8 * ((lane >> 3) & 1);
    const int lseg = lane >> 4;
    const int brow = (lane & 7) + 8 * (lane >> 4);
    const int bseg = (lane >> 3) & 1;

    // load both Q head tiles
    for (int e = tid; e < 1024; e += 256) {
        int th = e >> 9, idx = e & 511;
        int r = idx >> 3, s = idx & 7;
        *(uint4*)(sh + th * (64 * AQST) + r * AQST + s * 8) =
            *(const uint4*)(QKV + (size_t)(b * SEQ + q0 + r) * NQKV + (h0 + th) * DKH + s * 8);
    }

    auto prefetch = [&](int tile) {
        unsigned kb = Kb0 + (tile % 3) * ATILE_B;
        unsigned vb = Vb0 + (tile % 3) * ATILE_B;
        const __half* base = QKV + (size_t)(b * SEQ + tile * 64) * NQKV + DMODEL + g * DKH;
#pragma unroll
        for (int it = 0; it < 2; it++) {
            int i = tid + it * 256;
            int r = i >> 3, s = i & 7;
            const __half* rowp = base + (size_t)r * NQKV + s * 8;
            cp16(kb + (r * AQST + s * 8) * 2, rowp);
            cp16(vb + (r * AQST + s * 8) * 2, rowp + GDK);
        }
        CP_COMMIT();
    };

    prefetch(0);
    prefetch(1);
    __syncthreads();   // Q tiles visible

    // hoist Q fragments (loop-invariant)
    const unsigned Qb = Qb0 + hh * ATILE_B;
    unsigned qf[4][4];
#pragma unroll
    for (int ks = 0; ks < 4; ks++)
        ldm_x4(qf[ks], Qb + ((wq0 + lrow) * AQST + ks * 16 + 8 * lseg) * 2);

    float oacc[8][4];
#pragma unroll
    for (int nt = 0; nt < 8; nt++)
#pragma unroll
        for (int f = 0; f < 4; f++) oacc[nt][f] = 0.0f;
    float mA = -1e30f, mB = -1e30f, lA = 0.0f, lB = 0.0f;

    const int NT = SEQ / 64;
    for (int t = 0; t < NT; t++) {
        if (t < NT - 1) { CP_WAIT(1); }
        else            { CP_WAIT(0); }
        __syncthreads();                 // tile t visible; stage (t+2)%3 free
        if (t + 2 < NT) prefetch(t + 2);

        const unsigned Ks = Kb0 + (t % 3) * ATILE_B;
        const unsigned Vs = Vb0 + (t % 3) * ATILE_B;

        // S = Q K^T
        float sacc[8][4];
#pragma unroll
        for (int nt = 0; nt < 8; nt++)
#pragma unroll
            for (int f = 0; f < 4; f++) sacc[nt][f] = 0.0f;

#pragma unroll
        for (int ks = 0; ks < 4; ks++) {
            int kb = ks * 16;
#pragma unroll
            for (int np = 0; np < 4; np++) {
                unsigned bq[4];
                ldm_x4(bq, Ks + ((np * 16 + brow) * AQST + kb + 8 * bseg) * 2);
                mma_f16(sacc[2 * np],     qf[ks], bq[0], bq[1]);
                mma_f16(sacc[2 * np + 1], qf[ks], bq[2], bq[3]);
            }
        }

        // online softmax (log2 domain; scale folded into Wq)
        float rmaxA = -1e30f, rmaxB = -1e30f;
#pragma unroll
        for (int nt = 0; nt < 8; nt++) {
            rmaxA = fmaxf(rmaxA, fmaxf(sacc[nt][0], sacc[nt][1]));
            rmaxB = fmaxf(rmaxB, fmaxf(sacc[nt][2], sacc[nt][3]));
        }
#pragma unroll
        for (int o = 1; o <= 2; o <<= 1) {
            rmaxA = fmaxf(rmaxA, __shfl_xor_sync(0xffffffffu, rmaxA, o));
            rmaxB = fmaxf(rmaxB, __shfl_xor_sync(0xffffffffu, rmaxB, o));
        }
        float mnA = fmaxf(mA, rmaxA), mnB = fmaxf(mB, rmaxB);

        unsigned ph[8][2];
        float lsA = 0.0f, lsB = 0.0f;
#pragma unroll
        for (int nt = 0; nt < 8; nt++) {
            float p0 = exp2f(sacc[nt][0] - mnA);
            float p1 = exp2f(sacc[nt][1] - mnA);
            float p2 = exp2f(sacc[nt][2] - mnB);
            float p3 = exp2f(sacc[nt][3] - mnB);
            lsA += p0 + p1;  lsB += p2 + p3;
            ph[nt][0] = h2u(p0, p1);
            ph[nt][1] = h2u(p2, p3);
        }
#pragma unroll
        for (int o = 1; o <= 2; o <<= 1) {
            lsA += __shfl_xor_sync(0xffffffffu, lsA, o);
            lsB += __shfl_xor_sync(0xffffffffu, lsB, o);
        }
        float alA = exp2f(mA - mnA), alB = exp2f(mB - mnB);
        lA = lA * alA + lsA;  lB = lB * alB + lsB;
        mA = mnA;             mB = mnB;
#pragma unroll
        for (int nt = 0; nt < 8; nt++) {
            oacc[nt][0] *= alA; oacc[nt][1] *= alA;
            oacc[nt][2] *= alB; oacc[nt][3] *= alB;
        }

        // O += P V
#pragma unroll
        for (int ks = 0; ks < 4; ks++) {
            int kb = ks * 16;
            unsigned a[4];
            a[0] = ph[2 * ks][0];
            a[1] = ph[2 * ks][1];
            a[2] = ph[2 * ks + 1][0];
            a[3] = ph[2 * ks + 1][1];
#pragma unroll
            for (int np = 0; np < 4; np++) {
                unsigned bv[4];
                ldm_x4_t(bv, Vs + ((kb + lrow) * AQST + np * 16 + 8 * lseg) * 2);
                mma_f16(oacc[2 * np],     a, bv[0], bv[1]);
                mma_f16(oacc[2 * np + 1], a, bv[2], bv[3]);
            }
        }
        // no trailing barrier: next iteration's sync provides it
    }

    // epilogue
    float invA = 1.0f / lA, invB = 1.0f / lB;
    size_t rowA = (size_t)(b * SEQ + q0 + wq0 + grp) * DMODEL + (h0 + hh) * DKH;
    size_t rowB = rowA + (size_t)8 * DMODEL;
#pragma unroll
    for (int nt = 0; nt < 8; nt++) {
        int c = nt * 8 + 2 * tig;
        *(unsigned*)(O + rowA + c) = h2u(oacc[nt][0] * invA, oacc[nt][1] * invA);
        *(unsigned*)(O + rowB + c) = h2u(oacc[nt][2] * invB, oacc[nt][3] * invB);
    }
}

// ---------------- host ----------------
extern "C" void kernel_launch(void* const* d_in, const int* in_sizes, int n_in,
                              void* d_out, int out_size)
{
    const float* x  = (const float*)d_in[0];
    const float* Wq = (const float*)d_in[1];
    const float* bq = (const float*)d_in[2];
    const float* Wk = (const float*)d_in[3];
    const float* bk = (const float*)d_in[4];
    const float* Wv = (const float*)d_in[5];
    const float* bv = (const float*)d_in[6];
    const float* Wo = (const float*)d_in[7];
    const float* bo = (const float*)d_in[8];
    float* out = (float*)d_out;

    __half *xh, *QKVh, *Ch, *Wqkvt, *Wot;
    float* bqkv;
    cudaGetSymbolAddress((void**)&xh,    g_xh);
    cudaGetSymbolAddress((void**)&QKVh,  g_QKVh);
    cudaGetSymbolAddress((void**)&Ch,    g_Ch);
    cudaGetSymbolAddress((void**)&Wqkvt, g_Wqkvt);
    cudaGetSymbolAddress((void**)&Wot,   g_Wot);
    cudaGetSymbolAddress((void**)&bqkv,  g_bqkv);

    cudaFuncSetAttribute(gqa_attn_f16_kernel,
                         cudaFuncAttributeMaxDynamicSharedMemorySize, ATTN_SMEM);
    cudaFuncSetAttribute(gemm_f16_kernel<true>,
                         cudaFuncAttributeMaxDynamicSharedMemorySize, GEMM_SMEM);
    cudaFuncSetAttribute(gemm_f16_kernel<false>,
                         cudaFuncAttributeMaxDynamicSharedMemorySize, GEMM_SMEM);

    cvt_half_kernel<<<(MROWS * DMODEL / 4 + 255) / 256, 256>>>(x, xh, MROWS * DMODEL / 4);
    transpose_all_kernel<<<dim3(DMODEL / 32, DMODEL / 32, 4), 256>>>(
        Wq, Wk, Wv, Wo, Wqkvt, Wot);
    fuse_bias_kernel<<<(NQKV + 255) / 256, 256>>>(bq, bk, bv, bqkv);

    // fused QKV projection (N=3072)
    gemm_f16_kernel<true><<<dim3(NQKV / 128, MROWS / 128), 256, GEMM_SMEM>>>(
        xh, Wqkvt, bqkv, QKVh, NQKV, DMODEL);

    // attention: 2 heads per block
    gqa_attn_f16_kernel<<<dim3(SEQ / 64, NH / 2, BATCH), 256, ATTN_SMEM>>>(QKVh, Ch);

    // output projection -> fp32
    gemm_f16_kernel<false><<<dim3(DMODEL / 128, MROWS / 128), 256, GEMM_SMEM>>>(
        Ch, Wot, bo, out, DMODEL, DMODEL);
}

// round 16
// speedup vs baseline: 1.5165x; 1.5165x over previous
#include <cuda_runtime.h>
#include <cuda_fp16.h>

#define BATCH 2
#define SEQ   2048
#define DMODEL 2048
#define NH    32
#define NG    8
#define DKH   64
#define GDK   (NG * DKH)     // 512
#define NQKV  (DMODEL + 2 * GDK)   // 3072
#define MROWS (BATCH * SEQ)  // 4096
#define SCALE_Q 0.1803368801111204f   // 0.125 * log2(e)

// ---------------- scratch ----------------
__device__ __half g_xh   [MROWS * DMODEL];
__device__ __half g_QKVh [MROWS * NQKV];
__device__ __half g_Ch   [MROWS * DMODEL];
__device__ __half g_Wqkvt[NQKV * DMODEL];
__device__ __half g_Wot  [DMODEL * DMODEL];
__device__ float  g_bqkv [NQKV];

// ---------------- helpers ----------------
__device__ __forceinline__ unsigned smem_u32(const void* p) {
    unsigned a;
    asm("{ .reg .u64 t; cvta.to.shared.u64 t, %1; cvt.u32.u64 %0, t; }" : "=r"(a) : "l"(p));
    return a;
}
__device__ __forceinline__ void cp16(unsigned saddr, const void* g) {
    asm volatile("cp.async.cg.shared.global [%0], [%1], 16;" :: "r"(saddr), "l"(g));
}
#define CP_COMMIT() asm volatile("cp.async.commit_group;" ::: "memory")
#define CP_WAIT(n)  asm volatile("cp.async.wait_group %0;" :: "n"(n) : "memory")

__device__ __forceinline__ void ldm_x4(unsigned* r, unsigned saddr) {
    asm volatile("ldmatrix.sync.aligned.m8n8.x4.shared.b16 {%0,%1,%2,%3}, [%4];"
        : "=r"(r[0]), "=r"(r[1]), "=r"(r[2]), "=r"(r[3]) : "r"(saddr));
}
__device__ __forceinline__ void ldm_x4_t(unsigned* r, unsigned saddr) {
    asm volatile("ldmatrix.sync.aligned.m8n8.x4.trans.shared.b16 {%0,%1,%2,%3}, [%4];"
        : "=r"(r[0]), "=r"(r[1]), "=r"(r[2]), "=r"(r[3]) : "r"(saddr));
}
__device__ __forceinline__ void mma_f16(float* d, const unsigned* a, unsigned b0, unsigned b1) {
    asm volatile(
        "mma.sync.aligned.m16n8k16.row.col.f32.f16.f16.f32 "
        "{%0,%1,%2,%3}, {%4,%5,%6,%7}, {%8,%9}, {%0,%1,%2,%3};"
        : "+f"(d[0]), "+f"(d[1]), "+f"(d[2]), "+f"(d[3])
        : "r"(a[0]), "r"(a[1]), "r"(a[2]), "r"(a[3]), "r"(b0), "r"(b1));
}
__device__ __forceinline__ unsigned h2u(float a, float b) {
    __half2 h = __floats2half2_rn(a, b);
    return *reinterpret_cast<unsigned*>(&h);
}

// ---------------- prep kernels ----------------
__global__ __launch_bounds__(256) void cvt_half_kernel(
    const float* __restrict__ in, __half* __restrict__ out, int n4)
{
    int i = blockIdx.x * blockDim.x + threadIdx.x;
    if (i >= n4) return;
    float4 v = ((const float4*)in)[i];
    ((__half2*)out)[2 * i]     = __floats2half2_rn(v.x, v.y);
    ((__half2*)out)[2 * i + 1] = __floats2half2_rn(v.z, v.w);
}

// z = 0..3: weight transposes; z = 4: bias fusion
__global__ __launch_bounds__(256) void transpose_all_kernel(
    const float* __restrict__ Wq, const float* __restrict__ Wk,
    const float* __restrict__ Wv, const float* __restrict__ Wo,
    const float* __restrict__ bq, const float* __restrict__ bk,
    const float* __restrict__ bv,
    __half* __restrict__ Wqkvt, __half* __restrict__ Wot,
    float* __restrict__ bqkv)
{
    if (blockIdx.z == 4) {
        if (blockIdx.y != 0) return;
        int i = blockIdx.x * blockDim.x + threadIdx.x;
        if (i < DMODEL)                bqkv[i] = bq[i] * SCALE_Q;
        else if (i < DMODEL + GDK)     bqkv[i] = bk[i - DMODEL];
        else if (i < NQKV)             bqkv[i] = bv[i - DMODEL - GDK];
        return;
    }
    const float* W; __half* T; int N; float scale;
    switch (blockIdx.z) {
        case 0: W = Wq; T = Wqkvt;                                   N = DMODEL; scale = SCALE_Q; break;
        case 1: W = Wk; T = Wqkvt + (size_t)DMODEL * DMODEL;         N = GDK;    scale = 1.0f;    break;
        case 2: W = Wv; T = Wqkvt + (size_t)(DMODEL + GDK) * DMODEL; N = GDK;    scale = 1.0f;    break;
        default: W = Wo; T = Wot;                                    N = DMODEL; scale = 1.0f;    break;
    }
    int n0 = blockIdx.x * 32;
    if (n0 >= N) return;
    int k0 = blockIdx.y * 32;
    __shared__ float t[32][33];
    int tx = threadIdx.x & 31, ty = threadIdx.x >> 5;
#pragma unroll
    for (int s = 0; s < 4; s++)
        t[ty + 8 * s][tx] = W[(size_t)(k0 + ty + 8 * s) * N + n0 + tx];
    __syncthreads();
#pragma unroll
    for (int s = 0; s < 4; s++)
        T[(size_t)(n0 + ty + 8 * s) * DMODEL + k0 + tx] = __float2half(t[tx][ty + 8 * s] * scale);
}

// ---------------- fp16 GEMM: 128x128 CTA, 64x32 warp, BK=64, 2-stage ----------------
#define HST 72
#define TILE_H (128 * HST)
#define STG_H (2 * TILE_H)
#define GEMM_SMEM (2 * STG_H * 2)    // 73728 B

template <bool OUT_HALF>
__global__ __launch_bounds__(256, 2) void gemm_f16_kernel(
    const __half* __restrict__ A, const __half* __restrict__ Bt,
    const float* __restrict__ bias, void* __restrict__ Cout, int N, int K)
{
    extern __shared__ __half smh[];
    const unsigned sbase = smem_u32(smh);
    const int tid  = threadIdx.x;
    const int warp = tid >> 5;
    const int lane = tid & 31;
    const int grp  = lane >> 2;
    const int tig  = lane & 3;
    const int bm = blockIdx.y * 128;
    const int bn = blockIdx.x * 128;
    const int wm = (warp >> 2) * 64;
    const int wn = (warp & 3) * 32;

    const int lrow = (lane & 7) + 8 * ((lane >> 3) & 1);
    const int lseg = lane >> 4;
    const int brow = (lane & 7) + 8 * (lane >> 4);
    const int bseg = (lane >> 3) & 1;

    float acc[4][4][4];
#pragma unroll
    for (int mt = 0; mt < 4; mt++)
#pragma unroll
        for (int nt = 0; nt < 4; nt++)
#pragma unroll
            for (int f = 0; f < 4; f++) acc[mt][nt][f] = 0.0f;

    const int NC = K >> 6;

    auto load_chunk = [&](int kc, int st) {
        unsigned ab = sbase + st * (STG_H * 2);
        unsigned bb = ab + TILE_H * 2;
        const __half* gA = A  + (size_t)bm * K + kc * 64;
        const __half* gB = Bt + (size_t)bn * K + kc * 64;
#pragma unroll
        for (int it = 0; it < 4; it++) {
            int i = tid + it * 256;
            int r = i >> 3, ch = i & 7;
            cp16(ab + (r * HST + ch * 8) * 2, gA + (size_t)r * K + ch * 8);
        }
#pragma unroll
        for (int it = 0; it < 4; it++) {
            int i = tid + it * 256;
            int r = i >> 3, ch = i & 7;
            cp16(bb + (r * HST + ch * 8) * 2, gB + (size_t)r * K + ch * 8);
        }
        CP_COMMIT();
    };

    load_chunk(0, 0);
    for (int c = 0; c < NC; c++) {
        const int st = c & 1;
        if (c + 1 < NC) { load_chunk(c + 1, st ^ 1); CP_WAIT(1); }
        else            { CP_WAIT(0); }
        __syncthreads();

        const unsigned sA = sbase + st * (STG_H * 2);
        const unsigned sB = sA + TILE_H * 2;
#pragma unroll
        for (int kb = 0; kb < 64; kb += 16) {
            unsigned a[4][4], bq[2][4];
#pragma unroll
            for (int mt = 0; mt < 4; mt++)
                ldm_x4(a[mt], sA + ((wm + mt * 16 + lrow) * HST + kb + 8 * lseg) * 2);
#pragma unroll
            for (int np = 0; np < 2; np++)
                ldm_x4(bq[np], sB + ((wn + np * 16 + brow) * HST + kb + 8 * bseg) * 2);
#pragma unroll
            for (int mt = 0; mt < 4; mt++)
#pragma unroll
                for (int np = 0; np < 2; np++) {
                    mma_f16(acc[mt][2 * np],     a[mt], bq[np][0], bq[np][1]);
                    mma_f16(acc[mt][2 * np + 1], a[mt], bq[np][2], bq[np][3]);
                }
        }
        __syncthreads();
    }

#pragma unroll
    for (int mt = 0; mt < 4; mt++) {
        int r0 = bm + wm + mt * 16 + grp;
#pragma unroll
        for (int nt = 0; nt < 4; nt++) {
            int c0 = bn + wn + nt * 8 + 2 * tig;
            float b0 = bias[c0], b1 = bias[c0 + 1];
            float v00 = acc[mt][nt][0] + b0, v01 = acc[mt][nt][1] + b1;
            float v10 = acc[mt][nt][2] + b0, v11 = acc[mt][nt][3] + b1;
            if (OUT_HALF) {
                __half* C = (__half*)Cout;
                *(unsigned*)(C + (size_t)r0 * N + c0)       = h2u(v00, v01);
                *(unsigned*)(C + (size_t)(r0 + 8) * N + c0) = h2u(v10, v11);
            } else {
                float* C = (float*)Cout;
                *(float2*)(C + (size_t)r0 * N + c0)       = make_float2(v00, v01);
                *(float2*)(C + (size_t)(r0 + 8) * N + c0) = make_float2(v10, v11);
            }
        }
    }
}

// ---------------- flash attention: 2 heads/block, exp2 domain ----------------
#define AQST 72
#define ATILE_B (64 * AQST * 2)
#define ATTN_SMEM (6 * ATILE_B)            // 55296 B

__global__ __launch_bounds__(256) void gqa_attn_f16_kernel(
    const __half* __restrict__ QKV, __half* __restrict__ O)
{
    extern __shared__ __half sh[];
    const unsigned sb = smem_u32(sh);
    const unsigned Qb0 = sb;
    const unsigned Kb0 = sb + 2 * ATILE_B;
    const unsigned Vb0 = sb + 4 * ATILE_B;

    const int h0 = blockIdx.y * 2;
    const int b  = blockIdx.z;
    const int g  = h0 >> 2;
    const int q0 = blockIdx.x * 64;
    const int tid  = threadIdx.x;
    const int warp = tid >> 5;
    const int hh   = warp >> 2;
    const int lane = tid & 31;
    const int grp  = lane >> 2;
    const int tig  = lane & 3;
    const int wq0 = (warp & 3) * 16;

    const int lrow = (lane & 7) + 8 * ((lane >> 3) & 1);
    const int lseg = lane >> 4;
    const int brow = (lane & 7) + 8 * (lane >> 4);
    const int bseg = (lane >> 3) & 1;

    for (int e = tid; e < 1024; e += 256) {
        int th = e >> 9, idx = e & 511;
        int r = idx >> 3, s = idx & 7;
        *(uint4*)(sh + th * (64 * AQST) + r * AQST + s * 8) =
            *(const uint4*)(QKV + (size_t)(b * SEQ + q0 + r) * NQKV + (h0 + th) * DKH + s * 8);
    }

    auto prefetch = [&](int kt, int st) {
        unsigned kb = Kb0 + st * ATILE_B;
        unsigned vb = Vb0 + st * ATILE_B;
        const __half* base = QKV + (size_t)(b * SEQ + kt) * NQKV + DMODEL + g * DKH;
#pragma unroll
        for (int it = 0; it < 2; it++) {
            int i = tid + it * 256;
            int r = i >> 3, s = i & 7;
            const __half* rowp = base + (size_t)r * NQKV + s * 8;
            cp16(kb + (r * AQST + s * 8) * 2, rowp);
            cp16(vb + (r * AQST + s * 8) * 2, rowp + GDK);
        }
        CP_COMMIT();
    };

    prefetch(0, 0);
    __syncthreads();

    const unsigned Qb = Qb0 + hh * ATILE_B;
    unsigned qf[4][4];
#pragma unroll
    for (int ks = 0; ks < 4; ks++)
        ldm_x4(qf[ks], Qb + ((wq0 + lrow) * AQST + ks * 16 + 8 * lseg) * 2);

    float oacc[8][4];
#pragma unroll
    for (int nt = 0; nt < 8; nt++)
#pragma unroll
        for (int f = 0; f < 4; f++) oacc[nt][f] = 0.0f;
    float mA = -1e30f, mB = -1e30f, lA = 0.0f, lB = 0.0f;

    const int NT = SEQ / 64;
    for (int t = 0; t < NT; t++) {
        const int st = t & 1;
        if (t + 1 < NT) { prefetch((t + 1) * 64, st ^ 1); CP_WAIT(1); }
        else            { CP_WAIT(0); }
        __syncthreads();

        const unsigned Ks = Kb0 + st * ATILE_B;
        const unsigned Vs = Vb0 + st * ATILE_B;

        float sacc[8][4];
#pragma unroll
        for (int nt = 0; nt < 8; nt++)
#pragma unroll
            for (int f = 0; f < 4; f++) sacc[nt][f] = 0.0f;

#pragma unroll
        for (int ks = 0; ks < 4; ks++) {
            int kb = ks * 16;
#pragma unroll
            for (int np = 0; np < 4; np++) {
                unsigned bq[4];
                ldm_x4(bq, Ks + ((np * 16 + brow) * AQST + kb + 8 * bseg) * 2);
                mma_f16(sacc[2 * np],     qf[ks], bq[0], bq[1]);
                mma_f16(sacc[2 * np + 1], qf[ks], bq[2], bq[3]);
            }
        }

        float rmaxA = -1e30f, rmaxB = -1e30f;
#pragma unroll
        for (int nt = 0; nt < 8; nt++) {
            rmaxA = fmaxf(rmaxA, fmaxf(sacc[nt][0], sacc[nt][1]));
            rmaxB = fmaxf(rmaxB, fmaxf(sacc[nt][2], sacc[nt][3]));
        }
#pragma unroll
        for (int o = 1; o <= 2; o <<= 1) {
            rmaxA = fmaxf(rmaxA, __shfl_xor_sync(0xffffffffu, rmaxA, o));
            rmaxB = fmaxf(rmaxB, __shfl_xor_sync(0xffffffffu, rmaxB, o));
        }
        float mnA = fmaxf(mA, rmaxA), mnB = fmaxf(mB, rmaxB);

        unsigned ph[8][2];
        float lsA = 0.0f, lsB = 0.0f;
#pragma unroll
        for (int nt = 0; nt < 8; nt++) {
            float p0 = exp2f(sacc[nt][0] - mnA);
            float p1 = exp2f(sacc[nt][1] - mnA);
            float p2 = exp2f(sacc[nt][2] - mnB);
            float p3 = exp2f(sacc[nt][3] - mnB);
            lsA += p0 + p1;  lsB += p2 + p3;
            ph[nt][0] = h2u(p0, p1);
            ph[nt][1] = h2u(p2, p3);
        }
#pragma unroll
        for (int o = 1; o <= 2; o <<= 1) {
            lsA += __shfl_xor_sync(0xffffffffu, lsA, o);
            lsB += __shfl_xor_sync(0xffffffffu, lsB, o);
        }
        float alA = exp2f(mA - mnA), alB = exp2f(mB - mnB);
        lA = lA * alA + lsA;  lB = lB * alB + lsB;
        mA = mnA;             mB = mnB;
#pragma unroll
        for (int nt = 0; nt < 8; nt++) {
            oacc[nt][0] *= alA; oacc[nt][1] *= alA;
            oacc[nt][2] *= alB; oacc[nt][3] *= alB;
        }

#pragma unroll
        for (int ks = 0; ks < 4; ks++) {
            int kb = ks * 16;
            unsigned a[4];
            a[0] = ph[2 * ks][0];
            a[1] = ph[2 * ks][1];
            a[2] = ph[2 * ks + 1][0];
            a[3] = ph[2 * ks + 1][1];
#pragma unroll
            for (int np = 0; np < 4; np++) {
                unsigned bv[4];
                ldm_x4_t(bv, Vs + ((kb + lrow) * AQST + np * 16 + 8 * lseg) * 2);
                mma_f16(oacc[2 * np],     a, bv[0], bv[1]);
                mma_f16(oacc[2 * np + 1], a, bv[2], bv[3]);
            }
        }
        __syncthreads();
    }

    float invA = 1.0f / lA, invB = 1.0f / lB;
    size_t rowA = (size_t)(b * SEQ + q0 + wq0 + grp) * DMODEL + (h0 + hh) * DKH;
    size_t rowB = rowA + (size_t)8 * DMODEL;
#pragma unroll
    for (int nt = 0; nt < 8; nt++) {
        int c = nt * 8 + 2 * tig;
        *(unsigned*)(O + rowA + c) = h2u(oacc[nt][0] * invA, oacc[nt][1] * invA);
        *(unsigned*)(O + rowB + c) = h2u(oacc[nt][2] * invB, oacc[nt][3] * invB);
    }
}

// ---------------- host ----------------
extern "C" void kernel_launch(void* const* d_in, const int* in_sizes, int n_in,
                              void* d_out, int out_size)
{
    const float* x  = (const float*)d_in[0];
    const float* Wq = (const float*)d_in[1];
    const float* bq = (const float*)d_in[2];
    const float* Wk = (const float*)d_in[3];
    const float* bk = (const float*)d_in[4];
    const float* Wv = (const float*)d_in[5];
    const float* bv = (const float*)d_in[6];
    const float* Wo = (const float*)d_in[7];
    const float* bo = (const float*)d_in[8];
    float* out = (float*)d_out;

    __half *xh, *QKVh, *Ch, *Wqkvt, *Wot;
    float* bqkv;
    cudaGetSymbolAddress((void**)&xh,    g_xh);
    cudaGetSymbolAddress((void**)&QKVh,  g_QKVh);
    cudaGetSymbolAddress((void**)&Ch,    g_Ch);
    cudaGetSymbolAddress((void**)&Wqkvt, g_Wqkvt);
    cudaGetSymbolAddress((void**)&Wot,   g_Wot);
    cudaGetSymbolAddress((void**)&bqkv,  g_bqkv);

    cudaFuncSetAttribute(gqa_attn_f16_kernel,
                         cudaFuncAttributeMaxDynamicSharedMemorySize, ATTN_SMEM);
    cudaFuncSetAttribute(gemm_f16_kernel<true>,
                         cudaFuncAttributeMaxDynamicSharedMemorySize, GEMM_SMEM);
    cudaFuncSetAttribute(gemm_f16_kernel<false>,
                         cudaFuncAttributeMaxDynamicSharedMemorySize, GEMM_SMEM);

    cvt_half_kernel<<<(MROWS * DMODEL / 4 + 255) / 256, 256>>>(x, xh, MROWS * DMODEL / 4);
    transpose_all_kernel<<<dim3(DMODEL / 32, DMODEL / 32, 5), 256>>>(
        Wq, Wk, Wv, Wo, bq, bk, bv, Wqkvt, Wot, bqkv);

    // fused QKV projection (N=3072), 128x128 tiles, 2 CTA/SM
    gemm_f16_kernel<true><<<dim3(NQKV / 128, MROWS / 128), 256, GEMM_SMEM>>>(
        xh, Wqkvt, bqkv, QKVh, NQKV, DMODEL);

    // attention: 2 heads per block
    gqa_attn_f16_kernel<<<dim3(SEQ / 64, NH / 2, BATCH), 256, ATTN_SMEM>>>(QKVh, Ch);

    // output projection -> fp32
    gemm_f16_kernel<false><<<dim3(DMODEL / 128, MROWS / 128), 256, GEMM_SMEM>>>(
        Ch, Wot, bo, out, DMODEL, DMODEL);
}

// round 17
// speedup vs baseline: 1.5814x; 1.0428x over previous
#include <cuda_runtime.h>
#include <cuda_fp16.h>

#define BATCH 2
#define SEQ   2048
#define DMODEL 2048
#define NH    32
#define NG    8
#define DKH   64
#define GDK   (NG * DKH)     // 512
#define NQKV  (DMODEL + 2 * GDK)   // 3072
#define MROWS (BATCH * SEQ)  // 4096
#define SCALE_Q 0.1803368801111204f   // 0.125 * log2(e)

// ---------------- scratch ----------------
__device__ __half g_xh   [MROWS * DMODEL];
__device__ __half g_QKVh [MROWS * NQKV];
__device__ __half g_Ch   [MROWS * DMODEL];
__device__ __half g_Wqkvt[NQKV * DMODEL];
__device__ __half g_Wot  [DMODEL * DMODEL];
__device__ float  g_bqkv [NQKV];

// ---------------- helpers ----------------
__device__ __forceinline__ unsigned smem_u32(const void* p) {
    unsigned a;
    asm("{ .reg .u64 t; cvta.to.shared.u64 t, %1; cvt.u32.u64 %0, t; }" : "=r"(a) : "l"(p));
    return a;
}
__device__ __forceinline__ void cp16(unsigned saddr, const void* g) {
    asm volatile("cp.async.cg.shared.global [%0], [%1], 16;" :: "r"(saddr), "l"(g));
}
#define CP_COMMIT() asm volatile("cp.async.commit_group;" ::: "memory")
#define CP_WAIT(n)  asm volatile("cp.async.wait_group %0;" :: "n"(n) : "memory")

__device__ __forceinline__ void ldm_x4(unsigned* r, unsigned saddr) {
    asm volatile("ldmatrix.sync.aligned.m8n8.x4.shared.b16 {%0,%1,%2,%3}, [%4];"
        : "=r"(r[0]), "=r"(r[1]), "=r"(r[2]), "=r"(r[3]) : "r"(saddr));
}
__device__ __forceinline__ void ldm_x4_t(unsigned* r, unsigned saddr) {
    asm volatile("ldmatrix.sync.aligned.m8n8.x4.trans.shared.b16 {%0,%1,%2,%3}, [%4];"
        : "=r"(r[0]), "=r"(r[1]), "=r"(r[2]), "=r"(r[3]) : "r"(saddr));
}
__device__ __forceinline__ void ldm_x2_t(unsigned* r, unsigned saddr) {
    asm volatile("ldmatrix.sync.aligned.m8n8.x2.trans.shared.b16 {%0,%1}, [%2];"
        : "=r"(r[0]), "=r"(r[1]) : "r"(saddr));
}
__device__ __forceinline__ void mma_f16(float* d, const unsigned* a, unsigned b0, unsigned b1) {
    asm volatile(
        "mma.sync.aligned.m16n8k16.row.col.f32.f16.f16.f32 "
        "{%0,%1,%2,%3}, {%4,%5,%6,%7}, {%8,%9}, {%0,%1,%2,%3};"
        : "+f"(d[0]), "+f"(d[1]), "+f"(d[2]), "+f"(d[3])
        : "r"(a[0]), "r"(a[1]), "r"(a[2]), "r"(a[3]), "r"(b0), "r"(b1));
}
__device__ __forceinline__ unsigned h2u(float a, float b) {
    __half2 h = __floats2half2_rn(a, b);
    return *reinterpret_cast<unsigned*>(&h);
}

// ---------------- prep kernels ----------------
__global__ __launch_bounds__(256) void cvt_half_kernel(
    const float* __restrict__ in, __half* __restrict__ out, int n4)
{
    int i = blockIdx.x * blockDim.x + threadIdx.x;
    if (i >= n4) return;
    float4 v = ((const float4*)in)[i];
    ((__half2*)out)[2 * i]     = __floats2half2_rn(v.x, v.y);
    ((__half2*)out)[2 * i + 1] = __floats2half2_rn(v.z, v.w);
}

// z = 0..3: weight transposes; z = 4: bias fusion
__global__ __launch_bounds__(256) void transpose_all_kernel(
    const float* __restrict__ Wq, const float* __restrict__ Wk,
    const float* __restrict__ Wv, const float* __restrict__ Wo,
    const float* __restrict__ bq, const float* __restrict__ bk,
    const float* __restrict__ bv,
    __half* __restrict__ Wqkvt, __half* __restrict__ Wot,
    float* __restrict__ bqkv)
{
    if (blockIdx.z == 4) {
        if (blockIdx.y != 0) return;
        int i = blockIdx.x * blockDim.x + threadIdx.x;
        if (i < DMODEL)                bqkv[i] = bq[i] * SCALE_Q;
        else if (i < DMODEL + GDK)     bqkv[i] = bk[i - DMODEL];
        else if (i < NQKV)             bqkv[i] = bv[i - DMODEL - GDK];
        return;
    }
    const float* W; __half* T; int N; float scale;
    switch (blockIdx.z) {
        case 0: W = Wq; T = Wqkvt;                                   N = DMODEL; scale = SCALE_Q; break;
        case 1: W = Wk; T = Wqkvt + (size_t)DMODEL * DMODEL;         N = GDK;    scale = 1.0f;    break;
        case 2: W = Wv; T = Wqkvt + (size_t)(DMODEL + GDK) * DMODEL; N = GDK;    scale = 1.0f;    break;
        default: W = Wo; T = Wot;                                    N = DMODEL; scale = 1.0f;    break;
    }
    int n0 = blockIdx.x * 32;
    if (n0 >= N) return;
    int k0 = blockIdx.y * 32;
    __shared__ float t[32][33];
    int tx = threadIdx.x & 31, ty = threadIdx.x >> 5;
#pragma unroll
    for (int s = 0; s < 4; s++)
        t[ty + 8 * s][tx] = W[(size_t)(k0 + ty + 8 * s) * N + n0 + tx];
    __syncthreads();
#pragma unroll
    for (int s = 0; s < 4; s++)
        T[(size_t)(n0 + ty + 8 * s) * DMODEL + k0 + tx] = __float2half(t[tx][ty + 8 * s] * scale);
}

// ---------------- fp16 GEMM: 128x128 CTA, 64x32 warp, BK=64, 2-stage ----------------
#define HST 72
#define TILE_H (128 * HST)
#define STG_H (2 * TILE_H)
#define GEMM_SMEM (2 * STG_H * 2)    // 73728 B

template <bool OUT_HALF>
__global__ __launch_bounds__(256, 2) void gemm_f16_kernel(
    const __half* __restrict__ A, const __half* __restrict__ Bt,
    const float* __restrict__ bias, void* __restrict__ Cout, int N, int K)
{
    extern __shared__ __half smh[];
    const unsigned sbase = smem_u32(smh);
    const int tid  = threadIdx.x;
    const int warp = tid >> 5;
    const int lane = tid & 31;
    const int grp  = lane >> 2;
    const int tig  = lane & 3;
    const int bm = blockIdx.y * 128;
    const int bn = blockIdx.x * 128;
    const int wm = (warp >> 2) * 64;
    const int wn = (warp & 3) * 32;

    const int lrow = (lane & 7) + 8 * ((lane >> 3) & 1);
    const int lseg = lane >> 4;
    const int brow = (lane & 7) + 8 * (lane >> 4);
    const int bseg = (lane >> 3) & 1;

    float acc[4][4][4];
#pragma unroll
    for (int mt = 0; mt < 4; mt++)
#pragma unroll
        for (int nt = 0; nt < 4; nt++)
#pragma unroll
            for (int f = 0; f < 4; f++) acc[mt][nt][f] = 0.0f;

    const int NC = K >> 6;

    auto load_chunk = [&](int kc, int st) {
        unsigned ab = sbase + st * (STG_H * 2);
        unsigned bb = ab + TILE_H * 2;
        const __half* gA = A  + (size_t)bm * K + kc * 64;
        const __half* gB = Bt + (size_t)bn * K + kc * 64;
#pragma unroll
        for (int it = 0; it < 4; it++) {
            int i = tid + it * 256;
            int r = i >> 3, ch = i & 7;
            cp16(ab + (r * HST + ch * 8) * 2, gA + (size_t)r * K + ch * 8);
        }
#pragma unroll
        for (int it = 0; it < 4; it++) {
            int i = tid + it * 256;
            int r = i >> 3, ch = i & 7;
            cp16(bb + (r * HST + ch * 8) * 2, gB + (size_t)r * K + ch * 8);
        }
        CP_COMMIT();
    };

    load_chunk(0, 0);
    for (int c = 0; c < NC; c++) {
        const int st = c & 1;
        if (c + 1 < NC) { load_chunk(c + 1, st ^ 1); CP_WAIT(1); }
        else            { CP_WAIT(0); }
        __syncthreads();

        const unsigned sA = sbase + st * (STG_H * 2);
        const unsigned sB = sA + TILE_H * 2;
#pragma unroll
        for (int kb = 0; kb < 64; kb += 16) {
            unsigned a[4][4], bq[2][4];
#pragma unroll
            for (int mt = 0; mt < 4; mt++)
                ldm_x4(a[mt], sA + ((wm + mt * 16 + lrow) * HST + kb + 8 * lseg) * 2);
#pragma unroll
            for (int np = 0; np < 2; np++)
                ldm_x4(bq[np], sB + ((wn + np * 16 + brow) * HST + kb + 8 * bseg) * 2);
#pragma unroll
            for (int mt = 0; mt < 4; mt++)
#pragma unroll
                for (int np = 0; np < 2; np++) {
                    mma_f16(acc[mt][2 * np],     a[mt], bq[np][0], bq[np][1]);
                    mma_f16(acc[mt][2 * np + 1], a[mt], bq[np][2], bq[np][3]);
                }
        }
        __syncthreads();
    }

#pragma unroll
    for (int mt = 0; mt < 4; mt++) {
        int r0 = bm + wm + mt * 16 + grp;
#pragma unroll
        for (int nt = 0; nt < 4; nt++) {
            int c0 = bn + wn + nt * 8 + 2 * tig;
            float b0 = bias[c0], b1 = bias[c0 + 1];
            float v00 = acc[mt][nt][0] + b0, v01 = acc[mt][nt][1] + b1;
            float v10 = acc[mt][nt][2] + b0, v11 = acc[mt][nt][3] + b1;
            if (OUT_HALF) {
                __half* C = (__half*)Cout;
                *(unsigned*)(C + (size_t)r0 * N + c0)       = h2u(v00, v01);
                *(unsigned*)(C + (size_t)(r0 + 8) * N + c0) = h2u(v10, v11);
            } else {
                float* C = (float*)Cout;
                *(float2*)(C + (size_t)r0 * N + c0)       = make_float2(v00, v01);
                *(float2*)(C + (size_t)(r0 + 8) * N + c0) = make_float2(v10, v11);
            }
        }
    }
}

// ---------------- flash attention: 2 heads/block, l via ones-column mma ----------------
#define AQST 72
#define ATILE_B (64 * AQST * 2)
#define ATTN_SMEM (6 * ATILE_B)            // 55296 B

__global__ __launch_bounds__(256, 2) void gqa_attn_f16_kernel(
    const __half* __restrict__ QKV, __half* __restrict__ O)
{
    extern __shared__ __half sh[];
    const unsigned sb = smem_u32(sh);
    const unsigned Qb0 = sb;
    const unsigned Kb0 = sb + 2 * ATILE_B;
    const unsigned Vb0 = sb + 4 * ATILE_B;

    const int h0 = blockIdx.y * 2;
    const int b  = blockIdx.z;
    const int g  = h0 >> 2;
    const int q0 = blockIdx.x * 64;
    const int tid  = threadIdx.x;
    const int warp = tid >> 5;
    const int hh   = warp >> 2;
    const int lane = tid & 31;
    const int grp  = lane >> 2;
    const int tig  = lane & 3;
    const int wq0 = (warp & 3) * 16;

    const int lrow = (lane & 7) + 8 * ((lane >> 3) & 1);
    const int lseg = lane >> 4;
    const int brow = (lane & 7) + 8 * (lane >> 4);
    const int bseg = (lane >> 3) & 1;

    for (int e = tid; e < 1024; e += 256) {
        int th = e >> 9, idx = e & 511;
        int r = idx >> 3, s = idx & 7;
        *(uint4*)(sh + th * (64 * AQST) + r * AQST + s * 8) =
            *(const uint4*)(QKV + (size_t)(b * SEQ + q0 + r) * NQKV + (h0 + th) * DKH + s * 8);
    }

    // V pad columns (64..71) for both stages: [1.0, 0, 0, 0, 0, 0, 0, 0]
    for (int e = tid; e < 128; e += 256) {
        int st = e >> 6, r = e & 63;
        uint4 pad = make_uint4(0x00003C00u, 0u, 0u, 0u);
        *(uint4*)(sh + (4 + st) * (64 * AQST) + r * AQST + 64) = pad;
    }

    auto prefetch = [&](int kt, int st) {
        unsigned kb = Kb0 + st * ATILE_B;
        unsigned vb = Vb0 + st * ATILE_B;
        const __half* base = QKV + (size_t)(b * SEQ + kt) * NQKV + DMODEL + g * DKH;
#pragma unroll
        for (int it = 0; it < 2; it++) {
            int i = tid + it * 256;
            int r = i >> 3, s = i & 7;
            const __half* rowp = base + (size_t)r * NQKV + s * 8;
            cp16(kb + (r * AQST + s * 8) * 2, rowp);
            cp16(vb + (r * AQST + s * 8) * 2, rowp + GDK);
        }
        CP_COMMIT();
    };

    prefetch(0, 0);
    __syncthreads();

    const unsigned Qb = Qb0 + hh * ATILE_B;
    unsigned qf[4][4];
#pragma unroll
    for (int ks = 0; ks < 4; ks++)
        ldm_x4(qf[ks], Qb + ((wq0 + lrow) * AQST + ks * 16 + 8 * lseg) * 2);

    float oacc[8][4];
#pragma unroll
    for (int nt = 0; nt < 8; nt++)
#pragma unroll
        for (int f = 0; f < 4; f++) oacc[nt][f] = 0.0f;
    float lacc[4] = {0.0f, 0.0f, 0.0f, 0.0f};   // col 64 = row sums (l)
    float mA = -1e30f, mB = -1e30f;

    const int NT = SEQ / 64;
    for (int t = 0; t < NT; t++) {
        const int st = t & 1;
        if (t + 1 < NT) { prefetch((t + 1) * 64, st ^ 1); CP_WAIT(1); }
        else            { CP_WAIT(0); }
        __syncthreads();

        const unsigned Ks = Kb0 + st * ATILE_B;
        const unsigned Vs = Vb0 + st * ATILE_B;

        float sacc[8][4];
#pragma unroll
        for (int nt = 0; nt < 8; nt++)
#pragma unroll
            for (int f = 0; f < 4; f++) sacc[nt][f] = 0.0f;

#pragma unroll
        for (int ks = 0; ks < 4; ks++) {
            int kb = ks * 16;
#pragma unroll
            for (int np = 0; np < 4; np++) {
                unsigned bq[4];
                ldm_x4(bq, Ks + ((np * 16 + brow) * AQST + kb + 8 * bseg) * 2);
                mma_f16(sacc[2 * np],     qf[ks], bq[0], bq[1]);
                mma_f16(sacc[2 * np + 1], qf[ks], bq[2], bq[3]);
            }
        }

        // online softmax: max reduction only (sums come from the ones-column mma)
        float rmaxA = -1e30f, rmaxB = -1e30f;
#pragma unroll
        for (int nt = 0; nt < 8; nt++) {
            rmaxA = fmaxf(rmaxA, fmaxf(sacc[nt][0], sacc[nt][1]));
            rmaxB = fmaxf(rmaxB, fmaxf(sacc[nt][2], sacc[nt][3]));
        }
#pragma unroll
        for (int o = 1; o <= 2; o <<= 1) {
            rmaxA = fmaxf(rmaxA, __shfl_xor_sync(0xffffffffu, rmaxA, o));
            rmaxB = fmaxf(rmaxB, __shfl_xor_sync(0xffffffffu, rmaxB, o));
        }
        float mnA = fmaxf(mA, rmaxA), mnB = fmaxf(mB, rmaxB);

        unsigned ph[8][2];
#pragma unroll
        for (int nt = 0; nt < 8; nt++) {
            float p0 = exp2f(sacc[nt][0] - mnA);
            float p1 = exp2f(sacc[nt][1] - mnA);
            float p2 = exp2f(sacc[nt][2] - mnB);
            float p3 = exp2f(sacc[nt][3] - mnB);
            ph[nt][0] = h2u(p0, p1);
            ph[nt][1] = h2u(p2, p3);
        }
        float alA = exp2f(mA - mnA), alB = exp2f(mB - mnB);
        mA = mnA;  mB = mnB;
#pragma unroll
        for (int nt = 0; nt < 8; nt++) {
            oacc[nt][0] *= alA; oacc[nt][1] *= alA;
            oacc[nt][2] *= alB; oacc[nt][3] *= alB;
        }
        lacc[0] *= alA; lacc[2] *= alB;

        // O += P V  (plus l += P * ones via pad column 64)
#pragma unroll
        for (int ks = 0; ks < 4; ks++) {
            int kb = ks * 16;
            unsigned a[4];
            a[0] = ph[2 * ks][0];
            a[1] = ph[2 * ks][1];
            a[2] = ph[2 * ks + 1][0];
            a[3] = ph[2 * ks + 1][1];
#pragma unroll
            for (int np = 0; np < 4; np++) {
                unsigned bv[4];
                ldm_x4_t(bv, Vs + ((kb + lrow) * AQST + np * 16 + 8 * lseg) * 2);
                mma_f16(oacc[2 * np],     a, bv[0], bv[1]);
                mma_f16(oacc[2 * np + 1], a, bv[2], bv[3]);
            }
            unsigned bv2[2];
            ldm_x2_t(bv2, Vs + ((kb + lrow) * AQST + 64) * 2);
            mma_f16(lacc, a, bv2[0], bv2[1]);
        }
        __syncthreads();
    }

    // broadcast l from the tig==0 lane of each row group
    float lAv = __shfl_sync(0xffffffffu, lacc[0], lane & ~3);
    float lBv = __shfl_sync(0xffffffffu, lacc[2], lane & ~3);
    float invA = 1.0f / lAv, invB = 1.0f / lBv;
    size_t rowA = (size_t)(b * SEQ + q0 + wq0 + grp) * DMODEL + (h0 + hh) * DKH;
    size_t rowB = rowA + (size_t)8 * DMODEL;
#pragma unroll
    for (int nt = 0; nt < 8; nt++) {
        int c = nt * 8 + 2 * tig;
        *(unsigned*)(O + rowA + c) = h2u(oacc[nt][0] * invA, oacc[nt][1] * invA);
        *(unsigned*)(O + rowB + c) = h2u(oacc[nt][2] * invB, oacc[nt][3] * invB);
    }
}

// ---------------- host ----------------
extern "C" void kernel_launch(void* const* d_in, const int* in_sizes, int n_in,
                              void* d_out, int out_size)
{
    const float* x  = (const float*)d_in[0];
    const float* Wq = (const float*)d_in[1];
    const float* bq = (const float*)d_in[2];
    const float* Wk = (const float*)d_in[3];
    const float* bk = (const float*)d_in[4];
    const float* Wv = (const float*)d_in[5];
    const float* bv = (const float*)d_in[6];
    const float* Wo = (const float*)d_in[7];
    const float* bo = (const float*)d_in[8];
    float* out = (float*)d_out;

    __half *xh, *QKVh, *Ch, *Wqkvt, *Wot;
    float* bqkv;
    cudaGetSymbolAddress((void**)&xh,    g_xh);
    cudaGetSymbolAddress((void**)&QKVh,  g_QKVh);
    cudaGetSymbolAddress((void**)&Ch,    g_Ch);
    cudaGetSymbolAddress((void**)&Wqkvt, g_Wqkvt);
    cudaGetSymbolAddress((void**)&Wot,   g_Wot);
    cudaGetSymbolAddress((void**)&bqkv,  g_bqkv);

    cudaFuncSetAttribute(gqa_attn_f16_kernel,
                         cudaFuncAttributeMaxDynamicSharedMemorySize, ATTN_SMEM);
    cudaFuncSetAttribute(gemm_f16_kernel<true>,
                         cudaFuncAttributeMaxDynamicSharedMemorySize, GEMM_SMEM);
    cudaFuncSetAttribute(gemm_f16_kernel<false>,
                         cudaFuncAttributeMaxDynamicSharedMemorySize, GEMM_SMEM);

    cvt_half_kernel<<<(MROWS * DMODEL / 4 + 255) / 256, 256>>>(x, xh, MROWS * DMODEL / 4);
    transpose_all_kernel<<<dim3(DMODEL / 32, DMODEL / 32, 5), 256>>>(
        Wq, Wk, Wv, Wo, bq, bk, bv, Wqkvt, Wot, bqkv);

    // fused QKV projection (N=3072), 128x128 tiles, 2 CTA/SM
    gemm_f16_kernel<true><<<dim3(NQKV / 128, MROWS / 128), 256, GEMM_SMEM>>>(
        xh, Wqkvt, bqkv, QKVh, NQKV, DMODEL);

    // attention: 2 heads per block, l via ones-column
    gqa_attn_f16_kernel<<<dim3(SEQ / 64, NH / 2, BATCH), 256, ATTN_SMEM>>>(QKVh, Ch);

    // output projection -> fp32
    gemm_f16_kernel<false><<<dim3(DMODEL / 128, MROWS / 128), 256, GEMM_SMEM>>>(
        Ch, Wot, bo, out, DMODEL, DMODEL);
}